// round 5
// baseline (speedup 1.0000x reference)
#include <cuda_runtime.h>
#include <cuda_fp16.h>
#include <cstdint>

// CIN via mma.sync (base-ISA tensor cores; tcgen05 unavailable on this
// harness's plain sm_103 ptxas target).
// out[r,j] = sum_{h,m} xl[r,h]*x0[r,m]*W[h*32+m,j]; r = b*16+d.
// R5: TM=64 / 128thr / grid=256 / 2 CTAs-per-SM, 3-stage B ring,
//     Z-generation pipelined one chunk ahead.

namespace {
constexpr int RTOT = 16384;           // 1024 batches * 16 emb rows
constexpr int NOUT = 128;
constexpr int OUTW = 384;
constexpr int TM   = 64;              // rows per CTA (= 4 batches)
constexpr int NCTA = RTOT / TM;       // 256
constexpr int NTHR = 128;

// SMEM layout (bytes)
constexpr int OFF_A    = 0;                        // 2 stages x 8192
constexpr int OFF_B    = 16384;                    // 3 stages x 16384
constexpr int OFF_X0   = 65536;                    // float[64][33]
constexpr int OFF_BIAS = OFF_X0 + 64 * 33 * 4;     // 73984
constexpr int SMEM_TOTAL = OFF_BIAS + 512;         // 74496
}

// device-global scratch (allocation-free rule)
__device__ __align__(16) __half g_Wt[128 * (1024 + 4096 + 4096)]; // [layer][j][k]
__device__ __align__(16) float  g_xlA[RTOT * NOUT];  // transposed [col][row]
__device__ __align__(16) float  g_xlB[RTOT * NOUT];

// ---------------- helpers ----------------
__device__ __forceinline__ uint32_t smem_u32(const void* p) {
    uint32_t a;
    asm("{ .reg .u64 t; cvta.to.shared.u64 t, %1; cvt.u32.u64 %0, t; }" : "=r"(a) : "l"(p));
    return a;
}
__device__ __forceinline__ void ldsm4(uint32_t* r, uint32_t addr) {
    asm volatile("ldmatrix.sync.aligned.m8n8.x4.shared.b16 {%0,%1,%2,%3}, [%4];"
                 : "=r"(r[0]), "=r"(r[1]), "=r"(r[2]), "=r"(r[3]) : "r"(addr));
}
__device__ __forceinline__ void mma16816(float* c, const uint32_t* a, const uint32_t* b) {
    asm volatile("mma.sync.aligned.m16n8k16.row.col.f32.f16.f16.f32 "
                 "{%0,%1,%2,%3}, {%4,%5,%6,%7}, {%8,%9}, {%0,%1,%2,%3};"
                 : "+f"(c[0]), "+f"(c[1]), "+f"(c[2]), "+f"(c[3])
                 : "r"(a[0]), "r"(a[1]), "r"(a[2]), "r"(a[3]), "r"(b[0]), "r"(b[1]));
}
#define CP_ASYNC16(dst, src) \
    asm volatile("cp.async.cg.shared.global [%0], [%1], 16;" :: "r"(dst), "l"(src) : "memory")
#define CP_COMMIT()  asm volatile("cp.async.commit_group;" ::: "memory")
#define CP_WAIT0()   asm volatile("cp.async.wait_group 0;" ::: "memory")
#define CP_WAIT1()   asm volatile("cp.async.wait_group 1;" ::: "memory")

// ---------------- W transpose + fp16 convert ----------------
template <int LAYER>
__global__ void wprep(const float* __restrict__ W) {
    constexpr int K    = (LAYER == 0) ? 1024 : 4096;
    constexpr int WOFF = (LAYER == 0) ? 0 : (LAYER == 1 ? 131072 : 655360);
    __half* Wt = g_Wt + WOFF;
    __shared__ float s[32][129];
    const int k0 = blockIdx.x * 32;
    const int t  = threadIdx.x;
#pragma unroll
    for (int i = 0; i < 16; i++) {
        int idx = t + i * 256;
        int kk = idx >> 7, j = idx & 127;
        s[kk][j] = W[(size_t)(k0 + kk) * 128 + j];
    }
    __syncthreads();
    const int j = t >> 1, hb = t & 1;
#pragma unroll
    for (int r = 0; r < 2; r++) {
        uint32_t w[4];
#pragma unroll
        for (int e = 0; e < 4; e++) {
            int kk = hb * 16 + r * 8 + e * 2;
            __half2 h2 = __floats2half2_rn(s[kk][j], s[kk + 1][j]);
            w[e] = *reinterpret_cast<uint32_t*>(&h2);
        }
        *reinterpret_cast<uint4*>(Wt + (size_t)j * K + k0 + hb * 16 + r * 8) =
            make_uint4(w[0], w[1], w[2], w[3]);
    }
}

// ---------------- main layer kernel ----------------
template <int LAYER>
__global__ __launch_bounds__(NTHR, 2)
void cin_mma(const float* __restrict__ inputs,
             const float* __restrict__ bias,
             float* __restrict__ out)
{
    constexpr int  K    = (LAYER == 0) ? 1024 : 4096;
    constexpr int  WOFF = (LAYER == 0) ? 0 : (LAYER == 1 ? 131072 : 655360);
    constexpr int  NC   = K / 64;          // 64-wide K chunks
    constexpr bool RELU = (LAYER < 2);
    constexpr bool WXL  = (LAYER < 2);

    extern __shared__ char smem[];
    const uint32_t sb = smem_u32(smem);

    const int tid  = threadIdx.x;
    const int wid  = tid >> 5;
    const int lane = tid & 31;
    const int blk  = blockIdx.x;
    const int R0   = blk * TM;

    const __half* Wt     = g_Wt + WOFF;
    const float*  xl_in  = (LAYER == 2) ? g_xlB : g_xlA;
    float*        xl_out = (LAYER == 0) ? g_xlA : g_xlB;

    // ---- B chunk prefetch into SW128-swizzled [n=128][k=64] stage (16KB) ----
    auto issue_b = [&](int cc) {
        const int s = cc % 3;
        const __half* wsrc = Wt + cc * 64;
        const uint32_t bbase = sb + OFF_B + s * 16384;
#pragma unroll
        for (int i = 0; i < 8; i++) {
            int idx = tid + i * NTHR;
            int j = idx >> 3, q = idx & 7;
            const __half* g = wsrc + (size_t)j * K + q * 8;
            uint32_t d = bbase + j * 128 + ((q * 16) ^ ((j & 7) << 4));
            CP_ASYNC16(d, g);
        }
        CP_COMMIT();
    };

    issue_b(0);
    if (NC > 1) issue_b(1);

    // ---- x0 tile (4 batches, contiguous 2048 floats) + bias -> SMEM ----
    {
        const float* src = inputs + (size_t)blk * 2048;
        float* x0sw = reinterpret_cast<float*>(smem + OFF_X0);
#pragma unroll
        for (int i = 0; i < 16; i++) {
            int idx = tid + i * NTHR;
            int bb = idx >> 9, m = (idx >> 4) & 31, d = idx & 15;
            x0sw[(bb * 16 + d) * 33 + m] = src[idx];
        }
        reinterpret_cast<float*>(smem + OFF_BIAS)[tid] = bias[tid];
    }
    __syncthreads();

    // ---- per-thread Z-gen setup: row = tid>>1 (0..63), half = tid&1 ----
    const int row  = tid >> 1;
    const int half = tid & 1;
    const float* x0s = reinterpret_cast<const float*>(smem + OFF_X0);
    float x0r[32];
#pragma unroll
    for (int m = 0; m < 32; m++) x0r[m] = x0s[row * 33 + m];
    const uint32_t xorv = (uint32_t)(row & 7) << 4;
    char* const arow_ptr = smem + OFF_A + row * 128;

    auto gen_z = [&](int cc) {   // generate Z chunk cc into A[cc&1]
        const int h = cc * 2 + half;
        float xlv;
        if (LAYER == 0) xlv = x0s[row * 33 + h];
        else            xlv = __ldg(&xl_in[(size_t)h * RTOT + R0 + row]);
        char* base = arow_ptr + (cc & 1) * 8192;
#pragma unroll
        for (int q = 0; q < 4; q++) {
            uint32_t w[4];
#pragma unroll
            for (int e = 0; e < 4; e++) {
                const int m = q * 8 + e * 2;
                __half2 h2 = __floats2half2_rn(xlv * x0r[m], xlv * x0r[m + 1]);
                w[e] = *reinterpret_cast<uint32_t*>(&h2);
            }
            const uint32_t off = (uint32_t)(half * 64 + q * 16) ^ xorv;
            *reinterpret_cast<uint4*>(base + off) = make_uint4(w[0], w[1], w[2], w[3]);
        }
    };

    gen_z(0);   // prologue: A[0]

    // ---- accumulators: warp tile 64(M) x 32(N) ----
    float acc[4][4][4];
#pragma unroll
    for (int mt = 0; mt < 4; mt++)
#pragma unroll
        for (int nt = 0; nt < 4; nt++)
#pragma unroll
            for (int e = 0; e < 4; e++) acc[mt][nt][e] = 0.f;

    const int ncol = wid * 32;     // warp N base
    const int g    = lane >> 3;    // ldmatrix address group

    // ================= main K loop =================
    for (int c = 0; c < NC; c++) {
        const int sA = c & 1;
        const int sB = c % 3;

        // B(c) landed: exact outstanding-group count
        if (c + 1 < NC) CP_WAIT1();
        else            CP_WAIT0();
        __syncthreads();           // A[sA] gen'd by all; B[sB] visible to all

        if (c + 2 < NC) issue_b(c + 2);   // stage (c+2)%3 last read in iter c-1
        if (c + 1 < NC) gen_z(c + 1);     // A[sA^1] last read in iter c-1

        // ---- compute chunk c: 4 k16 steps x (4 A-ldsm + 1 B-ldsm + 16 mma) ----
        const uint32_t abase = sb + OFF_A + sA * 8192;
        const uint32_t bbase = sb + OFF_B + sB * 16384;
#pragma unroll
        for (int ks = 0; ks < 4; ks++) {
            const int k0 = ks * 16;
            uint32_t afr[4][4];
#pragma unroll
            for (int mt = 0; mt < 4; mt++) {
                const int ar = mt * 16 + (g & 1) * 8 + (lane & 7);
                const int ak = k0 + (g >> 1) * 8;
                ldsm4(afr[mt], abase + ar * 128 + (((uint32_t)ak * 2) ^ ((ar & 7) << 4)));
            }
            uint32_t bfr[4][2];
#pragma unroll
            for (int bt = 0; bt < 2; bt++) {
                const int br = ncol + bt * 16 + (g >> 1) * 8 + (lane & 7);
                const int bk = k0 + (g & 1) * 8;
                uint32_t r[4];
                ldsm4(r, bbase + br * 128 + (((uint32_t)bk * 2) ^ ((br & 7) << 4)));
                bfr[bt * 2][0] = r[0]; bfr[bt * 2][1] = r[1];
                bfr[bt * 2 + 1][0] = r[2]; bfr[bt * 2 + 1][1] = r[3];
            }
#pragma unroll
            for (int mt = 0; mt < 4; mt++)
#pragma unroll
                for (int nt = 0; nt < 4; nt++)
                    mma16816(acc[mt][nt], afr[mt], bfr[nt]);
        }
    }

    // ================= epilogue =================
    const float* biass = reinterpret_cast<const float*>(smem + OFF_BIAS);
#pragma unroll
    for (int mt = 0; mt < 4; mt++) {
        const int batch = blk * 4 + mt;              // one m16 tile == one batch
        const int r0 = R0 + mt * 16 + (lane >> 2);
#pragma unroll
        for (int nt = 0; nt < 4; nt++) {
            const int j0 = ncol + nt * 8 + (lane & 3) * 2;
            const float b0 = biass[j0], b1 = biass[j0 + 1];
            float v0 = acc[mt][nt][0] + b0;
            float v1 = acc[mt][nt][1] + b1;
            float v2 = acc[mt][nt][2] + b0;
            float v3 = acc[mt][nt][3] + b1;
            if (RELU) {
                v0 = fmaxf(v0, 0.f); v1 = fmaxf(v1, 0.f);
                v2 = fmaxf(v2, 0.f); v3 = fmaxf(v3, 0.f);
            }
            if (WXL) {
                xl_out[(size_t)j0 * RTOT + r0]           = v0;
                xl_out[(size_t)(j0 + 1) * RTOT + r0]     = v1;
                xl_out[(size_t)j0 * RTOT + r0 + 8]       = v2;
                xl_out[(size_t)(j0 + 1) * RTOT + r0 + 8] = v3;
            }
            float s0 = v0 + v2, s1 = v1 + v3;        // rows r, r+8
            s0 += __shfl_xor_sync(0xffffffffu, s0, 4);
            s1 += __shfl_xor_sync(0xffffffffu, s1, 4);
            s0 += __shfl_xor_sync(0xffffffffu, s0, 8);
            s1 += __shfl_xor_sync(0xffffffffu, s1, 8);
            s0 += __shfl_xor_sync(0xffffffffu, s0, 16);
            s1 += __shfl_xor_sync(0xffffffffu, s1, 16);
            if (lane < 4) {
                float* dst = out + (size_t)batch * OUTW + LAYER * NOUT + ncol + nt * 8 + lane * 2;
                dst[0] = s0;
                dst[1] = s1;
            }
        }
    }
}

// ---------------- host ----------------
extern "C" void kernel_launch(void* const* d_in, const int* in_sizes, int n_in,
                              void* d_out, int out_size)
{
    const float* inputs = (const float*)d_in[0];
    const float* W0     = (const float*)d_in[1];
    const float* b0     = (const float*)d_in[2];
    const float* W1     = (const float*)d_in[3];
    const float* b1     = (const float*)d_in[4];
    const float* W2     = (const float*)d_in[5];
    const float* b2     = (const float*)d_in[6];
    float* out = (float*)d_out;

    cudaFuncSetAttribute(cin_mma<0>, cudaFuncAttributeMaxDynamicSharedMemorySize, SMEM_TOTAL);
    cudaFuncSetAttribute(cin_mma<1>, cudaFuncAttributeMaxDynamicSharedMemorySize, SMEM_TOTAL);
    cudaFuncSetAttribute(cin_mma<2>, cudaFuncAttributeMaxDynamicSharedMemorySize, SMEM_TOTAL);

    wprep<0><<<32,  256>>>(W0);
    wprep<1><<<128, 256>>>(W1);
    wprep<2><<<128, 256>>>(W2);

    cin_mma<0><<<NCTA, NTHR, SMEM_TOTAL>>>(inputs, b0, out);
    cin_mma<1><<<NCTA, NTHR, SMEM_TOTAL>>>(inputs, b1, out);
    cin_mma<2><<<NCTA, NTHR, SMEM_TOTAL>>>(inputs, b2, out);
}

// round 6
// speedup vs baseline: 1.0815x; 1.0815x over previous
#include <cuda_runtime.h>
#include <cuda_fp16.h>
#include <cstdint>

// CIN via mma.sync (base-ISA tensor cores; tcgen05 unavailable on this
// harness's plain sm_103 ptxas target).
// out[r,j] = sum_{h,m} xl[r,h]*x0[r,m]*W[h*32+m,j]; r = b*16+d.
// R6: K-chunk 128 (one barrier per 128-K), 2-stage A/B rings,
//     B prefetch hidden under a full chunk of mma.

namespace {
constexpr int RTOT = 16384;           // 1024 batches * 16 emb rows
constexpr int NOUT = 128;
constexpr int OUTW = 384;
constexpr int TM   = 64;              // rows per CTA (= 4 batches)
constexpr int NCTA = RTOT / TM;       // 256
constexpr int NTHR = 128;
constexpr int KC   = 128;             // K per chunk

// SMEM layout (bytes)
constexpr int OFF_A    = 0;                        // 2 stages x 16384 (64r x 128k)
constexpr int OFF_B    = 32768;                    // 2 stages x 32768 (128n x 128k)
constexpr int OFF_X0   = 98304;                    // float[64][33]
constexpr int OFF_BIAS = OFF_X0 + 64 * 33 * 4;     // 106752
constexpr int SMEM_TOTAL = OFF_BIAS + 512;         // 107264
}

// device-global scratch (allocation-free rule)
__device__ __align__(16) __half g_Wt[128 * (1024 + 4096 + 4096)]; // [layer][j][k]
__device__ __align__(16) float  g_xlA[RTOT * NOUT];  // transposed [col][row]
__device__ __align__(16) float  g_xlB[RTOT * NOUT];

// ---------------- helpers ----------------
__device__ __forceinline__ uint32_t smem_u32(const void* p) {
    uint32_t a;
    asm("{ .reg .u64 t; cvta.to.shared.u64 t, %1; cvt.u32.u64 %0, t; }" : "=r"(a) : "l"(p));
    return a;
}
__device__ __forceinline__ void ldsm4(uint32_t* r, uint32_t addr) {
    asm volatile("ldmatrix.sync.aligned.m8n8.x4.shared.b16 {%0,%1,%2,%3}, [%4];"
                 : "=r"(r[0]), "=r"(r[1]), "=r"(r[2]), "=r"(r[3]) : "r"(addr));
}
__device__ __forceinline__ void mma16816(float* c, const uint32_t* a, const uint32_t* b) {
    asm volatile("mma.sync.aligned.m16n8k16.row.col.f32.f16.f16.f32 "
                 "{%0,%1,%2,%3}, {%4,%5,%6,%7}, {%8,%9}, {%0,%1,%2,%3};"
                 : "+f"(c[0]), "+f"(c[1]), "+f"(c[2]), "+f"(c[3])
                 : "r"(a[0]), "r"(a[1]), "r"(a[2]), "r"(a[3]), "r"(b[0]), "r"(b[1]));
}
#define CP_ASYNC16(dst, src) \
    asm volatile("cp.async.cg.shared.global [%0], [%1], 16;" :: "r"(dst), "l"(src) : "memory")
#define CP_COMMIT()  asm volatile("cp.async.commit_group;" ::: "memory")
#define CP_WAIT0()   asm volatile("cp.async.wait_group 0;" ::: "memory")

// ---------------- W transpose + fp16 convert ----------------
template <int LAYER>
__global__ void wprep(const float* __restrict__ W) {
    constexpr int K    = (LAYER == 0) ? 1024 : 4096;
    constexpr int WOFF = (LAYER == 0) ? 0 : (LAYER == 1 ? 131072 : 655360);
    __half* Wt = g_Wt + WOFF;
    __shared__ float s[32][129];
    const int k0 = blockIdx.x * 32;
    const int t  = threadIdx.x;
#pragma unroll
    for (int i = 0; i < 16; i++) {
        int idx = t + i * 256;
        int kk = idx >> 7, j = idx & 127;
        s[kk][j] = W[(size_t)(k0 + kk) * 128 + j];
    }
    __syncthreads();
    const int j = t >> 1, hb = t & 1;
#pragma unroll
    for (int r = 0; r < 2; r++) {
        uint32_t w[4];
#pragma unroll
        for (int e = 0; e < 4; e++) {
            int kk = hb * 16 + r * 8 + e * 2;
            __half2 h2 = __floats2half2_rn(s[kk][j], s[kk + 1][j]);
            w[e] = *reinterpret_cast<uint32_t*>(&h2);
        }
        *reinterpret_cast<uint4*>(Wt + (size_t)j * K + k0 + hb * 16 + r * 8) =
            make_uint4(w[0], w[1], w[2], w[3]);
    }
}

// ---------------- main layer kernel ----------------
template <int LAYER>
__global__ __launch_bounds__(NTHR, 2)
void cin_mma(const float* __restrict__ inputs,
             const float* __restrict__ bias,
             float* __restrict__ out)
{
    constexpr int  K    = (LAYER == 0) ? 1024 : 4096;
    constexpr int  WOFF = (LAYER == 0) ? 0 : (LAYER == 1 ? 131072 : 655360);
    constexpr int  NC   = K / KC;          // 8 / 32 chunks
    constexpr bool RELU = (LAYER < 2);
    constexpr bool WXL  = (LAYER < 2);

    extern __shared__ char smem[];
    const uint32_t sb = smem_u32(smem);

    const int tid  = threadIdx.x;
    const int wid  = tid >> 5;
    const int lane = tid & 31;
    const int blk  = blockIdx.x;
    const int R0   = blk * TM;

    const __half* Wt     = g_Wt + WOFF;
    const float*  xl_in  = (LAYER == 2) ? g_xlB : g_xlA;
    float*        xl_out = (LAYER == 0) ? g_xlA : g_xlB;

    // ---- B chunk prefetch: [n=128][k=128] halves, 2 atom-cols of 16KB ----
    // byte layout: atom(k>>6)*16384 + n*128 + (((k&63)*2) ^ ((n&7)<<4))
    auto issue_b = [&](int cc) {
        const int s = cc & 1;
        const __half* wsrc = Wt + cc * KC;
        const uint32_t bbase = sb + OFF_B + s * 32768;
#pragma unroll
        for (int i = 0; i < 16; i++) {
            int idx = tid + i * NTHR;
            int j = idx >> 4, q = idx & 15;          // n-row, 16B unit (8 halves)
            const __half* g = wsrc + (size_t)j * K + q * 8;
            uint32_t d = bbase + (q >> 3) * 16384 + j * 128
                       + ((uint32_t)((q & 7) * 16) ^ ((j & 7) << 4));
            CP_ASYNC16(d, g);
        }
        CP_COMMIT();
    };

    issue_b(0);

    // ---- x0 tile (4 batches, contiguous 2048 floats) + bias -> SMEM ----
    {
        const float* src = inputs + (size_t)blk * 2048;
        float* x0sw = reinterpret_cast<float*>(smem + OFF_X0);
#pragma unroll
        for (int i = 0; i < 16; i++) {
            int idx = tid + i * NTHR;
            int bb = idx >> 9, m = (idx >> 4) & 31, d = idx & 15;
            x0sw[(bb * 16 + d) * 33 + m] = src[idx];
        }
        reinterpret_cast<float*>(smem + OFF_BIAS)[tid] = bias[tid];
    }
    __syncthreads();

    // ---- per-thread Z-gen setup: row = tid>>1 (0..63), half = k 64-block ----
    const int row  = tid >> 1;
    const int half = tid & 1;
    const float* x0s = reinterpret_cast<const float*>(smem + OFF_X0);
    float x0r[32];
#pragma unroll
    for (int m = 0; m < 32; m++) x0r[m] = x0s[row * 33 + m];
    const uint32_t xorv = (uint32_t)(row & 7) << 4;
    // A stage layout: atom(k>>6)*8192 + row*128 + (((k&63)*2) ^ ((row&7)<<4))
    char* const agen = smem + OFF_A + half * 8192 + row * 128;

    auto gen_z = [&](int cc) {   // generate Z chunk cc (k: half*64..half*64+63)
        char* base = agen + (cc & 1) * 16384;
#pragma unroll
        for (int p = 0; p < 2; p++) {            // two h values per 64-k block
            const int h = cc * 4 + half * 2 + p;
            float xlv;
            if (LAYER == 0) xlv = x0s[row * 33 + h];
            else            xlv = __ldg(&xl_in[(size_t)h * RTOT + R0 + row]);
#pragma unroll
            for (int q = 0; q < 4; q++) {
                uint32_t w[4];
#pragma unroll
                for (int e = 0; e < 4; e++) {
                    const int m = q * 8 + e * 2;
                    __half2 h2 = __floats2half2_rn(xlv * x0r[m], xlv * x0r[m + 1]);
                    w[e] = *reinterpret_cast<uint32_t*>(&h2);
                }
                const uint32_t off = (uint32_t)(p * 64 + q * 16) ^ xorv;
                *reinterpret_cast<uint4*>(base + off) = make_uint4(w[0], w[1], w[2], w[3]);
            }
        }
    };

    gen_z(0);   // prologue: A[0]

    // ---- accumulators: warp tile 64(M) x 32(N) ----
    float acc[4][4][4];
#pragma unroll
    for (int mt = 0; mt < 4; mt++)
#pragma unroll
        for (int nt = 0; nt < 4; nt++)
#pragma unroll
            for (int e = 0; e < 4; e++) acc[mt][nt][e] = 0.f;

    const int ncol = wid * 32;     // warp N base
    const int g    = lane >> 3;    // ldmatrix address group

    // ================= main K loop (one barrier per 128-K chunk) =============
    for (int c = 0; c < NC; c++) {
        const int sA = c & 1;
        const int sB = c & 1;

        CP_WAIT0();                // B(c) landed (only group outstanding)
        __syncthreads();           // A[sA] gen'd + B[sB] visible to all

        if (c + 1 < NC) {
            issue_b(c + 1);        // stage sB^1: last read in chunk c-1, safe
            gen_z(c + 1);          // A stage sA^1: last read in chunk c-1, safe
        }

        // ---- compute chunk c: 8 k16 steps x (4 A-ldsm + 2 B-ldsm + 16 mma) ----
        const uint32_t abase = sb + OFF_A + sA * 16384;
        const uint32_t bbase = sb + OFF_B + sB * 32768;
#pragma unroll
        for (int ks = 0; ks < 8; ks++) {
            const int k0 = ks * 16;
            uint32_t afr[4][4];
#pragma unroll
            for (int mt = 0; mt < 4; mt++) {
                const int ar = mt * 16 + (g & 1) * 8 + (lane & 7);
                const int ak = k0 + (g >> 1) * 8;
                ldsm4(afr[mt], abase + (ak >> 6) * 8192 + ar * 128
                               + (((uint32_t)(ak & 63) * 2) ^ ((ar & 7) << 4)));
            }
            uint32_t bfr[4][2];
#pragma unroll
            for (int bt = 0; bt < 2; bt++) {
                const int br = ncol + bt * 16 + (g >> 1) * 8 + (lane & 7);
                const int bk = k0 + (g & 1) * 8;
                uint32_t r[4];
                ldsm4(r, bbase + (bk >> 6) * 16384 + br * 128
                         + (((uint32_t)(bk & 63) * 2) ^ ((br & 7) << 4)));
                bfr[bt * 2][0] = r[0]; bfr[bt * 2][1] = r[1];
                bfr[bt * 2 + 1][0] = r[2]; bfr[bt * 2 + 1][1] = r[3];
            }
#pragma unroll
            for (int mt = 0; mt < 4; mt++)
#pragma unroll
                for (int nt = 0; nt < 4; nt++)
                    mma16816(acc[mt][nt], afr[mt], bfr[nt]);
        }
    }

    // ================= epilogue =================
    const float* biass = reinterpret_cast<const float*>(smem + OFF_BIAS);
#pragma unroll
    for (int mt = 0; mt < 4; mt++) {
        const int batch = blk * 4 + mt;              // one m16 tile == one batch
        const int r0 = R0 + mt * 16 + (lane >> 2);
#pragma unroll
        for (int nt = 0; nt < 4; nt++) {
            const int j0 = ncol + nt * 8 + (lane & 3) * 2;
            const float b0 = biass[j0], b1 = biass[j0 + 1];
            float v0 = acc[mt][nt][0] + b0;
            float v1 = acc[mt][nt][1] + b1;
            float v2 = acc[mt][nt][2] + b0;
            float v3 = acc[mt][nt][3] + b1;
            if (RELU) {
                v0 = fmaxf(v0, 0.f); v1 = fmaxf(v1, 0.f);
                v2 = fmaxf(v2, 0.f); v3 = fmaxf(v3, 0.f);
            }
            if (WXL) {
                xl_out[(size_t)j0 * RTOT + r0]           = v0;
                xl_out[(size_t)(j0 + 1) * RTOT + r0]     = v1;
                xl_out[(size_t)j0 * RTOT + r0 + 8]       = v2;
                xl_out[(size_t)(j0 + 1) * RTOT + r0 + 8] = v3;
            }
            float s0 = v0 + v2, s1 = v1 + v3;        // rows r, r+8
            s0 += __shfl_xor_sync(0xffffffffu, s0, 4);
            s1 += __shfl_xor_sync(0xffffffffu, s1, 4);
            s0 += __shfl_xor_sync(0xffffffffu, s0, 8);
            s1 += __shfl_xor_sync(0xffffffffu, s1, 8);
            s0 += __shfl_xor_sync(0xffffffffu, s0, 16);
            s1 += __shfl_xor_sync(0xffffffffu, s1, 16);
            if (lane < 4) {
                float* dst = out + (size_t)batch * OUTW + LAYER * NOUT + ncol + nt * 8 + lane * 2;
                dst[0] = s0;
                dst[1] = s1;
            }
        }
    }
}

// ---------------- host ----------------
extern "C" void kernel_launch(void* const* d_in, const int* in_sizes, int n_in,
                              void* d_out, int out_size)
{
    const float* inputs = (const float*)d_in[0];
    const float* W0     = (const float*)d_in[1];
    const float* b0     = (const float*)d_in[2];
    const float* W1     = (const float*)d_in[3];
    const float* b1     = (const float*)d_in[4];
    const float* W2     = (const float*)d_in[5];
    const float* b2     = (const float*)d_in[6];
    float* out = (float*)d_out;

    cudaFuncSetAttribute(cin_mma<0>, cudaFuncAttributeMaxDynamicSharedMemorySize, SMEM_TOTAL);
    cudaFuncSetAttribute(cin_mma<1>, cudaFuncAttributeMaxDynamicSharedMemorySize, SMEM_TOTAL);
    cudaFuncSetAttribute(cin_mma<2>, cudaFuncAttributeMaxDynamicSharedMemorySize, SMEM_TOTAL);

    wprep<0><<<32,  256>>>(W0);
    wprep<1><<<128, 256>>>(W1);
    wprep<2><<<128, 256>>>(W2);

    cin_mma<0><<<NCTA, NTHR, SMEM_TOTAL>>>(inputs, b0, out);
    cin_mma<1><<<NCTA, NTHR, SMEM_TOTAL>>>(inputs, b1, out);
    cin_mma<2><<<NCTA, NTHR, SMEM_TOTAL>>>(inputs, b2, out);
}

// round 7
// speedup vs baseline: 1.0859x; 1.0041x over previous
#include <cuda_runtime.h>
#include <cuda_fp16.h>
#include <cstdint>

// CIN via mma.sync (base-ISA tensor cores).
// out[r,j] = sum_{h,m} xl[r,h]*x0[r,m]*W[h*32+m,j]; r = b*16+d.
// R7: warp tile 64Mx64N, 2-way split-K within each 128-K chunk,
//     x0 in half2 registers (HMUL2 Z-gen), SMEM split-K reduction.

namespace {
constexpr int RTOT = 16384;           // 1024 batches * 16 emb rows
constexpr int NOUT = 128;
constexpr int OUTW = 384;
constexpr int TM   = 64;              // rows per CTA (= 4 batches)
constexpr int NCTA = RTOT / TM;       // 256
constexpr int NTHR = 128;
constexpr int KC   = 128;             // K per chunk

// SMEM layout (bytes)
constexpr int OFF_A    = 0;                        // 2 stages x 16384 (64r x 128k)
constexpr int OFF_B    = 32768;                    // 2 stages x 32768 (128n x 128k)
constexpr int OFF_X0   = 98304;                    // float[64][33]
constexpr int OFF_BIAS = OFF_X0 + 64 * 33 * 4;     // 106752
constexpr int SMEM_TOTAL = OFF_BIAS + 512;         // 107264
// epilogue split-K exchange reuses [OFF_A ..): float[64][132] = 33792 B
}

// device-global scratch (allocation-free rule)
__device__ __align__(16) __half g_Wt[128 * (1024 + 4096 + 4096)]; // [layer][j][k]
__device__ __align__(16) float  g_xlA[RTOT * NOUT];  // transposed [col][row]
__device__ __align__(16) float  g_xlB[RTOT * NOUT];

// ---------------- helpers ----------------
__device__ __forceinline__ uint32_t smem_u32(const void* p) {
    uint32_t a;
    asm("{ .reg .u64 t; cvta.to.shared.u64 t, %1; cvt.u32.u64 %0, t; }" : "=r"(a) : "l"(p));
    return a;
}
__device__ __forceinline__ void ldsm4(uint32_t* r, uint32_t addr) {
    asm volatile("ldmatrix.sync.aligned.m8n8.x4.shared.b16 {%0,%1,%2,%3}, [%4];"
                 : "=r"(r[0]), "=r"(r[1]), "=r"(r[2]), "=r"(r[3]) : "r"(addr));
}
__device__ __forceinline__ void mma16816(float* c, const uint32_t* a, const uint32_t* b) {
    asm volatile("mma.sync.aligned.m16n8k16.row.col.f32.f16.f16.f32 "
                 "{%0,%1,%2,%3}, {%4,%5,%6,%7}, {%8,%9}, {%0,%1,%2,%3};"
                 : "+f"(c[0]), "+f"(c[1]), "+f"(c[2]), "+f"(c[3])
                 : "r"(a[0]), "r"(a[1]), "r"(a[2]), "r"(a[3]), "r"(b[0]), "r"(b[1]));
}
#define CP_ASYNC16(dst, src) \
    asm volatile("cp.async.cg.shared.global [%0], [%1], 16;" :: "r"(dst), "l"(src) : "memory")
#define CP_COMMIT()  asm volatile("cp.async.commit_group;" ::: "memory")
#define CP_WAIT0()   asm volatile("cp.async.wait_group 0;" ::: "memory")

// ---------------- W transpose + fp16 convert ----------------
template <int LAYER>
__global__ void wprep(const float* __restrict__ W) {
    constexpr int K    = (LAYER == 0) ? 1024 : 4096;
    constexpr int WOFF = (LAYER == 0) ? 0 : (LAYER == 1 ? 131072 : 655360);
    __half* Wt = g_Wt + WOFF;
    __shared__ float s[32][129];
    const int k0 = blockIdx.x * 32;
    const int t  = threadIdx.x;
#pragma unroll
    for (int i = 0; i < 16; i++) {
        int idx = t + i * 256;
        int kk = idx >> 7, j = idx & 127;
        s[kk][j] = W[(size_t)(k0 + kk) * 128 + j];
    }
    __syncthreads();
    const int j = t >> 1, hb = t & 1;
#pragma unroll
    for (int r = 0; r < 2; r++) {
        uint32_t w[4];
#pragma unroll
        for (int e = 0; e < 4; e++) {
            int kk = hb * 16 + r * 8 + e * 2;
            __half2 h2 = __floats2half2_rn(s[kk][j], s[kk + 1][j]);
            w[e] = *reinterpret_cast<uint32_t*>(&h2);
        }
        *reinterpret_cast<uint4*>(Wt + (size_t)j * K + k0 + hb * 16 + r * 8) =
            make_uint4(w[0], w[1], w[2], w[3]);
    }
}

// ---------------- main layer kernel ----------------
template <int LAYER>
__global__ __launch_bounds__(NTHR, 2)
void cin_mma(const float* __restrict__ inputs,
             const float* __restrict__ bias,
             float* __restrict__ out)
{
    constexpr int  K    = (LAYER == 0) ? 1024 : 4096;
    constexpr int  WOFF = (LAYER == 0) ? 0 : (LAYER == 1 ? 131072 : 655360);
    constexpr int  NC   = K / KC;          // 8 / 32 chunks
    constexpr bool RELU = (LAYER < 2);
    constexpr bool WXL  = (LAYER < 2);

    extern __shared__ char smem[];
    const uint32_t sb = smem_u32(smem);

    const int tid  = threadIdx.x;
    const int wid  = tid >> 5;
    const int lane = tid & 31;
    const int blk  = blockIdx.x;
    const int R0   = blk * TM;

    const __half* Wt     = g_Wt + WOFF;
    const float*  xl_in  = (LAYER == 2) ? g_xlB : g_xlA;
    float*        xl_out = (LAYER == 0) ? g_xlA : g_xlB;

    // ---- B chunk prefetch: [n=128][k=128], 2 atom-cols of 16KB ----
    auto issue_b = [&](int cc) {
        const int s = cc & 1;
        const __half* wsrc = Wt + cc * KC;
        const uint32_t bbase = sb + OFF_B + s * 32768;
#pragma unroll
        for (int i = 0; i < 16; i++) {
            int idx = tid + i * NTHR;
            int j = idx >> 4, q = idx & 15;          // n-row, 16B unit
            const __half* g = wsrc + (size_t)j * K + q * 8;
            uint32_t d = bbase + (q >> 3) * 16384 + j * 128
                       + ((uint32_t)((q & 7) * 16) ^ ((j & 7) << 4));
            CP_ASYNC16(d, g);
        }
        CP_COMMIT();
    };

    issue_b(0);

    // ---- x0 tile (4 batches, contiguous 2048 floats) + bias -> SMEM ----
    {
        const float* src = inputs + (size_t)blk * 2048;
        float* x0sw = reinterpret_cast<float*>(smem + OFF_X0);
#pragma unroll
        for (int i = 0; i < 16; i++) {
            int idx = tid + i * NTHR;
            int bb = idx >> 9, m = (idx >> 4) & 31, d = idx & 15;
            x0sw[(bb * 16 + d) * 33 + m] = src[idx];
        }
        reinterpret_cast<float*>(smem + OFF_BIAS)[tid] = bias[tid];
    }
    __syncthreads();

    // ---- per-thread Z-gen setup: row = tid>>1 (0..63), half = k 64-block ----
    const int row  = tid >> 1;
    const int half = tid & 1;
    const float* x0s = reinterpret_cast<const float*>(smem + OFF_X0);
    __half2 x0h[16];                 // x0[row][2i], x0[row][2i+1] as half2
#pragma unroll
    for (int i = 0; i < 16; i++)
        x0h[i] = __floats2half2_rn(x0s[row * 33 + 2 * i], x0s[row * 33 + 2 * i + 1]);
    const uint32_t xorv = (uint32_t)(row & 7) << 4;
    // A stage layout: atom(k>>6)*8192 + row*128 + (((k&63)*2) ^ ((row&7)<<4))
    char* const agen = smem + OFF_A + half * 8192 + row * 128;

    auto gen_z = [&](int cc) {   // generate Z chunk cc (k: half*64..half*64+63)
        char* base = agen + (cc & 1) * 16384;
#pragma unroll
        for (int p = 0; p < 2; p++) {            // two h values per 64-k block
            const int h = cc * 4 + half * 2 + p;
            __half xlh;
            if (LAYER == 0) {
                __half2 hp = x0h[h >> 1];
                xlh = (h & 1) ? __high2half(hp) : __low2half(hp);
            } else {
                xlh = __float2half_rn(__ldg(&xl_in[(size_t)h * RTOT + R0 + row]));
            }
            const __half2 xl2 = __half2half2(xlh);
#pragma unroll
            for (int q = 0; q < 4; q++) {
                uint32_t w[4];
#pragma unroll
                for (int e = 0; e < 4; e++) {
                    __half2 h2 = __hmul2(x0h[q * 4 + e], xl2);
                    w[e] = *reinterpret_cast<uint32_t*>(&h2);
                }
                const uint32_t off = (uint32_t)(p * 64 + q * 16) ^ xorv;
                *reinterpret_cast<uint4*>(base + off) = make_uint4(w[0], w[1], w[2], w[3]);
            }
        }
    };

    gen_z(0);   // prologue: A[0]

    // ---- accumulators: warp tile 64(M) x 64(N), split-K 2-way ----
    float acc[4][8][4];
#pragma unroll
    for (int mt = 0; mt < 4; mt++)
#pragma unroll
        for (int nt = 0; nt < 8; nt++)
#pragma unroll
            for (int e = 0; e < 4; e++) acc[mt][nt][e] = 0.f;

    const int kg  = wid >> 1;       // K-half of each chunk (ks 0-3 / 4-7)
    const int ncb = (wid & 1) * 64; // warp N base
    const int g   = lane >> 3;      // ldmatrix address group

    // ================= main K loop (one barrier per 128-K chunk) =============
    for (int c = 0; c < NC; c++) {
        const int sA = c & 1;

        CP_WAIT0();                // B(c) landed (only group outstanding)
        __syncthreads();           // A[sA] gen'd + B[sA] visible to all

        if (c + 1 < NC) {
            issue_b(c + 1);        // stage sA^1: last read in chunk c-1, safe
            gen_z(c + 1);
        }

        // ---- compute chunk c: this warp does ks kg*4 .. kg*4+3 ----
        const uint32_t abase = sb + OFF_A + sA * 16384;
        const uint32_t bbase = sb + OFF_B + sA * 32768;
#pragma unroll
        for (int ks = 0; ks < 4; ks++) {
            const int k0 = (kg * 4 + ks) * 16;
            uint32_t afr[4][4];
#pragma unroll
            for (int mt = 0; mt < 4; mt++) {
                const int ar = mt * 16 + (g & 1) * 8 + (lane & 7);
                const int ak = k0 + (g >> 1) * 8;
                ldsm4(afr[mt], abase + (ak >> 6) * 8192 + ar * 128
                               + (((uint32_t)(ak & 63) * 2) ^ ((ar & 7) << 4)));
            }
            uint32_t bfr[8][2];
#pragma unroll
            for (int bt = 0; bt < 4; bt++) {
                const int br = ncb + bt * 16 + (g >> 1) * 8 + (lane & 7);
                const int bk = k0 + (g & 1) * 8;
                uint32_t r[4];
                ldsm4(r, bbase + (bk >> 6) * 16384 + br * 128
                         + (((uint32_t)(bk & 63) * 2) ^ ((br & 7) << 4)));
                bfr[bt * 2][0] = r[0]; bfr[bt * 2][1] = r[1];
                bfr[bt * 2 + 1][0] = r[2]; bfr[bt * 2 + 1][1] = r[3];
            }
#pragma unroll
            for (int mt = 0; mt < 4; mt++)
#pragma unroll
                for (int nt = 0; nt < 8; nt++)
                    mma16816(acc[mt][nt], afr[mt], bfr[nt]);
        }
    }

    // ================= split-K reduction via SMEM =================
    float* xch = reinterpret_cast<float*>(smem);   // [64][132], reuses A region
    __syncthreads();                                // everyone done with A/B
    if (kg == 1) {
#pragma unroll
        for (int mt = 0; mt < 4; mt++) {
            const int lr = mt * 16 + (lane >> 2);
#pragma unroll
            for (int nt = 0; nt < 8; nt++) {
                const int c0 = ncb + nt * 8 + (lane & 3) * 2;
                xch[lr * 132 + c0]           = acc[mt][nt][0];
                xch[lr * 132 + c0 + 1]       = acc[mt][nt][1];
                xch[(lr + 8) * 132 + c0]     = acc[mt][nt][2];
                xch[(lr + 8) * 132 + c0 + 1] = acc[mt][nt][3];
            }
        }
    }
    __syncthreads();
    if (kg == 0) {
#pragma unroll
        for (int mt = 0; mt < 4; mt++) {
            const int lr = mt * 16 + (lane >> 2);
#pragma unroll
            for (int nt = 0; nt < 8; nt++) {
                const int c0 = ncb + nt * 8 + (lane & 3) * 2;
                acc[mt][nt][0] += xch[lr * 132 + c0];
                acc[mt][nt][1] += xch[lr * 132 + c0 + 1];
                acc[mt][nt][2] += xch[(lr + 8) * 132 + c0];
                acc[mt][nt][3] += xch[(lr + 8) * 132 + c0 + 1];
            }
        }

        // ================= epilogue (warps 0,1 only) =================
        const float* biass = reinterpret_cast<const float*>(smem + OFF_BIAS);
#pragma unroll
        for (int mt = 0; mt < 4; mt++) {
            const int batch = blk * 4 + mt;              // one m16 tile == one batch
            const int r0 = R0 + mt * 16 + (lane >> 2);
#pragma unroll
            for (int nt = 0; nt < 8; nt++) {
                const int j0 = ncb + nt * 8 + (lane & 3) * 2;
                const float b0 = biass[j0], b1 = biass[j0 + 1];
                float v0 = acc[mt][nt][0] + b0;
                float v1 = acc[mt][nt][1] + b1;
                float v2 = acc[mt][nt][2] + b0;
                float v3 = acc[mt][nt][3] + b1;
                if (RELU) {
                    v0 = fmaxf(v0, 0.f); v1 = fmaxf(v1, 0.f);
                    v2 = fmaxf(v2, 0.f); v3 = fmaxf(v3, 0.f);
                }
                if (WXL) {
                    xl_out[(size_t)j0 * RTOT + r0]           = v0;
                    xl_out[(size_t)(j0 + 1) * RTOT + r0]     = v1;
                    xl_out[(size_t)j0 * RTOT + r0 + 8]       = v2;
                    xl_out[(size_t)(j0 + 1) * RTOT + r0 + 8] = v3;
                }
                float s0 = v0 + v2, s1 = v1 + v3;        // rows r, r+8
                s0 += __shfl_xor_sync(0xffffffffu, s0, 4);
                s1 += __shfl_xor_sync(0xffffffffu, s1, 4);
                s0 += __shfl_xor_sync(0xffffffffu, s0, 8);
                s1 += __shfl_xor_sync(0xffffffffu, s1, 8);
                s0 += __shfl_xor_sync(0xffffffffu, s0, 16);
                s1 += __shfl_xor_sync(0xffffffffu, s1, 16);
                if (lane < 4) {
                    float* dst = out + (size_t)batch * OUTW + LAYER * NOUT + j0 - (lane & 3) * 2 + (lane & 3) * 2;
                    dst = out + (size_t)batch * OUTW + LAYER * NOUT + ncb + nt * 8 + lane * 2;
                    dst[0] = s0;
                    dst[1] = s1;
                }
            }
        }
    }
}

// ---------------- host ----------------
extern "C" void kernel_launch(void* const* d_in, const int* in_sizes, int n_in,
                              void* d_out, int out_size)
{
    const float* inputs = (const float*)d_in[0];
    const float* W0     = (const float*)d_in[1];
    const float* b0     = (const float*)d_in[2];
    const float* W1     = (const float*)d_in[3];
    const float* b1     = (const float*)d_in[4];
    const float* W2     = (const float*)d_in[5];
    const float* b2     = (const float*)d_in[6];
    float* out = (float*)d_out;

    cudaFuncSetAttribute(cin_mma<0>, cudaFuncAttributeMaxDynamicSharedMemorySize, SMEM_TOTAL);
    cudaFuncSetAttribute(cin_mma<1>, cudaFuncAttributeMaxDynamicSharedMemorySize, SMEM_TOTAL);
    cudaFuncSetAttribute(cin_mma<2>, cudaFuncAttributeMaxDynamicSharedMemorySize, SMEM_TOTAL);

    wprep<0><<<32,  256>>>(W0);
    wprep<1><<<128, 256>>>(W1);
    wprep<2><<<128, 256>>>(W2);

    cin_mma<0><<<NCTA, NTHR, SMEM_TOTAL>>>(inputs, b0, out);
    cin_mma<1><<<NCTA, NTHR, SMEM_TOTAL>>>(inputs, b1, out);
    cin_mma<2><<<NCTA, NTHR, SMEM_TOTAL>>>(inputs, b2, out);
}